// round 1
// baseline (speedup 1.0000x reference)
#include <cuda_runtime.h>
#include <math.h>

// Problem constants
static const int Bc = 2;
static const int Sc = 2048;
static const int Dc = 1024;
static const int Hc = 16;
static const int DHc = 64;   // Dc / Hc

// Scratch (allocation-free rule: __device__ globals)
__device__ float g_q[Bc * Sc * Dc];
__device__ float g_k[Bc * Sc * Dc];
__device__ float g_v[Bc * Sc * Dc];
__device__ float g_ctx[Bc * Sc * Dc];
__device__ int   g_mask_mode;   // 0 = uint8, 1 = int32, 2 = float32

// ---------------------------------------------------------------------------
// Mask dtype detection: read first 4096 BYTES (in-bounds for all encodings).
//  - bool/uint8 storage: packed bytes -> some 32-bit words > 1 (and != 1.0f bits)
//  - int32 storage: all words in {0,1}
//  - float32 storage: words in {0, 0x3F800000}
// ---------------------------------------------------------------------------
__global__ void detect_mask_kernel(const unsigned int* __restrict__ m) {
    int t = threadIdx.x;
    int gt1 = 0, f1 = 0;
    #pragma unroll
    for (int i = 0; i < 4; i++) {
        unsigned int x = m[t * 4 + i];
        if (x > 1u && x != 0x3F800000u) gt1 = 1;
        if (x == 0x3F800000u) f1 = 1;
    }
    int any_gt1 = __syncthreads_or(gt1);
    int any_f1  = __syncthreads_or(f1);
    if (t == 0) {
        int mode;
        if (any_gt1)     mode = 0;   // packed bytes
        else if (any_f1) mode = 2;   // float 0.0 / 1.0
        else             mode = 1;   // int32 0 / 1
        g_mask_mode = mode;
    }
}

// ---------------------------------------------------------------------------
// Generic fp32 SGEMM tile body: C[64x64] += A[64xK] @ B[Kx64] (+ bias)
// 256 threads, 4x4 micro-tile per thread, BK=16, transposed-A smem tile so
// all inner-loop smem reads are LDS.128.
// ---------------------------------------------------------------------------
__device__ __forceinline__ void gemm_tile(
    const float* __restrict__ A, const float* __restrict__ Bm,
    const float* __restrict__ bias, float* __restrict__ C,
    int K, int lda, int ldb, int ldc, int row0, int col0)
{
    __shared__ float As[16][68];   // [k][m], pad 4 keeps 16B alignment, kills conflicts
    __shared__ float Bs[16][64];   // [k][n]

    const int t  = threadIdx.x;
    const int tx = t & 15;         // 0..15 -> n micro-tile
    const int ty = t >> 4;         // 0..15 -> m micro-tile

    const int ar = t >> 2;         // A-load row 0..63
    const int ak = (t & 3) << 2;   // A-load k 0,4,8,12
    const int br = t >> 4;         // B-load k-row 0..15
    const int bc = (t & 15) << 2;  // B-load col 0..60

    float acc[4][4] = {};

    for (int k0 = 0; k0 < K; k0 += 16) {
        float4 a4 = *(const float4*)(A + (size_t)(row0 + ar) * lda + k0 + ak);
        As[ak + 0][ar] = a4.x;
        As[ak + 1][ar] = a4.y;
        As[ak + 2][ar] = a4.z;
        As[ak + 3][ar] = a4.w;
        *(float4*)&Bs[br][bc] = *(const float4*)(Bm + (size_t)(k0 + br) * ldb + col0 + bc);
        __syncthreads();

        #pragma unroll
        for (int kk = 0; kk < 16; kk++) {
            float4 av = *(const float4*)&As[kk][ty << 2];
            float4 bv = *(const float4*)&Bs[kk][tx << 2];
            float a[4] = {av.x, av.y, av.z, av.w};
            float b[4] = {bv.x, bv.y, bv.z, bv.w};
            #pragma unroll
            for (int i = 0; i < 4; i++)
                #pragma unroll
                for (int j = 0; j < 4; j++)
                    acc[i][j] += a[i] * b[j];
        }
        __syncthreads();
    }

    float4 bvv = make_float4(0.f, 0.f, 0.f, 0.f);
    if (bias) bvv = *(const float4*)(bias + col0 + (tx << 2));
    #pragma unroll
    for (int i = 0; i < 4; i++) {
        int r = row0 + (ty << 2) + i;
        float4 o;
        o.x = acc[i][0] + bvv.x;
        o.y = acc[i][1] + bvv.y;
        o.z = acc[i][2] + bvv.z;
        o.w = acc[i][3] + bvv.w;
        *(float4*)(C + (size_t)r * ldc + col0 + (tx << 2)) = o;
    }
}

// C = A @ B + bias ; grid = (N/64, M/64)
__global__ void __launch_bounds__(256)
gemm_nn_kernel(const float* __restrict__ A, const float* __restrict__ Bm,
               const float* __restrict__ bias, float* __restrict__ C,
               int K, int lda, int ldb, int ldc)
{
    gemm_tile(A, Bm, bias, C, K, lda, ldb, ldc, blockIdx.y * 64, blockIdx.x * 64);
}

// ---------------------------------------------------------------------------
// scores[z, qi, kj] = mask[b,kj] ? (q . k) / 8 : -inf    (z = b*H + h)
// NT GEMM, K = 64 (one full pass in smem). grid = (S/64, S/64, B*H)
// ---------------------------------------------------------------------------
__global__ void __launch_bounds__(256)
scores_kernel(const float* __restrict__ q, const float* __restrict__ k,
              const void* __restrict__ maskp, float* __restrict__ attn)
{
    __shared__ float Qs[64][68];   // [d][m]
    __shared__ float Ks[64][68];   // [d][n]

    const int z = blockIdx.z;
    const int b = z >> 4;          // H = 16
    const int h = z & 15;

    const float* qb = q + ((size_t)b * Sc + blockIdx.y * 64) * Dc + h * DHc;
    const float* kb = k + ((size_t)b * Sc + blockIdx.x * 64) * Dc + h * DHc;

    const int t  = threadIdx.x;
    const int r  = t >> 2;          // 0..63
    const int d0 = (t & 3) << 4;    // 0,16,32,48

    #pragma unroll
    for (int j = 0; j < 4; j++) {
        int d = d0 + (j << 2);
        float4 a = *(const float4*)(qb + (size_t)r * Dc + d);
        Qs[d + 0][r] = a.x; Qs[d + 1][r] = a.y; Qs[d + 2][r] = a.z; Qs[d + 3][r] = a.w;
        float4 c = *(const float4*)(kb + (size_t)r * Dc + d);
        Ks[d + 0][r] = c.x; Ks[d + 1][r] = c.y; Ks[d + 2][r] = c.z; Ks[d + 3][r] = c.w;
    }
    __syncthreads();

    const int tx = t & 15, ty = t >> 4;
    float acc[4][4] = {};
    #pragma unroll 16
    for (int d = 0; d < 64; d++) {
        float4 av = *(const float4*)&Qs[d][ty << 2];
        float4 bv = *(const float4*)&Ks[d][tx << 2];
        float a[4] = {av.x, av.y, av.z, av.w};
        float bb[4] = {bv.x, bv.y, bv.z, bv.w};
        #pragma unroll
        for (int i = 0; i < 4; i++)
            #pragma unroll
            for (int j = 0; j < 4; j++)
                acc[i][j] += a[i] * bb[j];
    }

    const int kj0 = blockIdx.x * 64 + (tx << 2);
    const int mode = g_mask_mode;
    bool mv[4];
    #pragma unroll
    for (int j = 0; j < 4; j++) {
        size_t mi = (size_t)b * Sc + kj0 + j;
        if (mode == 0)      mv[j] = ((const unsigned char*)maskp)[mi] != 0;
        else if (mode == 1) mv[j] = ((const int*)maskp)[mi] != 0;
        else                mv[j] = ((const float*)maskp)[mi] != 0.0f;
    }

    const float scale = 0.125f;   // 1/sqrt(64)
    #pragma unroll
    for (int i = 0; i < 4; i++) {
        int qi = blockIdx.y * 64 + (ty << 2) + i;
        float4 o;
        o.x = mv[0] ? acc[i][0] * scale : -INFINITY;
        o.y = mv[1] ? acc[i][1] * scale : -INFINITY;
        o.z = mv[2] ? acc[i][2] * scale : -INFINITY;
        o.w = mv[3] ? acc[i][3] * scale : -INFINITY;
        *(float4*)(attn + ((size_t)z * Sc + qi) * Sc + kj0) = o;
    }
}

// ---------------------------------------------------------------------------
// In-place row softmax over attn rows of length S=2048. One block per row,
// 256 threads x 8 elements held in registers (single read + single write).
// ---------------------------------------------------------------------------
__global__ void __launch_bounds__(256)
softmax_kernel(float* __restrict__ attn)
{
    __shared__ float red[8];
    size_t row = blockIdx.x;
    float* p = attn + row * (size_t)Sc;
    const int t = threadIdx.x;

    float v[8];
    float mx = -INFINITY;
    #pragma unroll
    for (int i = 0; i < 8; i++) { v[i] = p[t + (i << 8)]; mx = fmaxf(mx, v[i]); }
    #pragma unroll
    for (int o = 16; o > 0; o >>= 1) mx = fmaxf(mx, __shfl_xor_sync(0xffffffffu, mx, o));
    if ((t & 31) == 0) red[t >> 5] = mx;
    __syncthreads();
    float m = fmaxf(fmaxf(fmaxf(red[0], red[1]), fmaxf(red[2], red[3])),
                    fmaxf(fmaxf(red[4], red[5]), fmaxf(red[6], red[7])));

    float s = 0.f;
    #pragma unroll
    for (int i = 0; i < 8; i++) { v[i] = __expf(v[i] - m); s += v[i]; }
    #pragma unroll
    for (int o = 16; o > 0; o >>= 1) s += __shfl_xor_sync(0xffffffffu, s, o);
    __syncthreads();
    if ((t & 31) == 0) red[t >> 5] = s;
    __syncthreads();
    float tot = red[0] + red[1] + red[2] + red[3] + red[4] + red[5] + red[6] + red[7];
    float inv = 1.0f / tot;
    #pragma unroll
    for (int i = 0; i < 8; i++) p[t + (i << 8)] = v[i] * inv;
}

// ---------------------------------------------------------------------------
// ctx[b, s, h*64 + d] = sum_j attn[z, s, j] * v[b, j, h*64 + d]
// grid = (1, S/64, B*H)
// ---------------------------------------------------------------------------
__global__ void __launch_bounds__(256)
ctx_kernel(const float* __restrict__ attn, const float* __restrict__ v,
           float* __restrict__ ctx)
{
    const int z = blockIdx.z;
    const int b = z >> 4;
    const int h = z & 15;
    const float* A  = attn + (size_t)z * Sc * Sc;
    const float* Bm = v + (size_t)b * Sc * Dc + h * DHc;
    float*       C  = ctx + (size_t)b * Sc * Dc + h * DHc;
    gemm_tile(A, Bm, nullptr, C, Sc /*K*/, Sc /*lda*/, Dc /*ldb*/, Dc /*ldc*/,
              blockIdx.y * 64, 0);
}

// ---------------------------------------------------------------------------
// Host launcher
// ---------------------------------------------------------------------------
extern "C" void kernel_launch(void* const* d_in, const int* in_sizes, int n_in,
                              void* d_out, int out_size)
{
    const float* qs  = (const float*)d_in[0];
    const float* ks  = (const float*)d_in[1];
    const float* vs  = (const float*)d_in[2];
    const void*  msk = d_in[3];
    const float* Wq  = (const float*)d_in[4];
    const float* bq  = (const float*)d_in[5];
    const float* Wk  = (const float*)d_in[6];
    const float* bk  = (const float*)d_in[7];
    const float* Wv  = (const float*)d_in[8];
    const float* bv  = (const float*)d_in[9];
    const float* Wo  = (const float*)d_in[10];
    const float* bo  = (const float*)d_in[11];

    float* out  = (float*)d_out;
    float* attn = out + (size_t)Bc * Sc * Dc;   // tuple (out, attn) flattened

    float *gq, *gk, *gv, *gc;
    cudaGetSymbolAddress((void**)&gq, g_q);
    cudaGetSymbolAddress((void**)&gk, g_k);
    cudaGetSymbolAddress((void**)&gv, g_v);
    cudaGetSymbolAddress((void**)&gc, g_ctx);

    const int M = Bc * Sc;   // 4096

    detect_mask_kernel<<<1, 256>>>((const unsigned int*)msk);

    dim3 blk(256);
    dim3 gproj(Dc / 64, M / 64);          // (16, 64)
    gemm_nn_kernel<<<gproj, blk>>>(qs, Wq, bq, gq, Dc, Dc, Dc, Dc);
    gemm_nn_kernel<<<gproj, blk>>>(ks, Wk, bk, gk, Dc, Dc, Dc, Dc);
    gemm_nn_kernel<<<gproj, blk>>>(vs, Wv, bv, gv, Dc, Dc, Dc, Dc);

    dim3 gsc(Sc / 64, Sc / 64, Bc * Hc);  // (32, 32, 32)
    scores_kernel<<<gsc, blk>>>(gq, gk, msk, attn);

    softmax_kernel<<<Bc * Hc * Sc, blk>>>(attn);

    dim3 gctx(1, Sc / 64, Bc * Hc);       // (1, 32, 32)
    ctx_kernel<<<gctx, blk>>>(attn, gv, gc);

    gemm_nn_kernel<<<gproj, blk>>>(gc, Wo, bo, out, Dc, Dc, Dc, Dc);
}

// round 7
// speedup vs baseline: 1.5034x; 1.5034x over previous
#include <cuda_runtime.h>
#include <math.h>

// Problem constants
static const int Bc = 2;
static const int Sc = 2048;
static const int Dc = 1024;
static const int Hc = 16;
static const int DHc = 64;   // Dc / Hc

// Scratch (allocation-free rule: __device__ globals)
__device__ float g_q[Bc * Sc * Dc];
__device__ float g_k[Bc * Sc * Dc];
__device__ float g_v[Bc * Sc * Dc];
__device__ float g_ctx[Bc * Sc * Dc];
__device__ float g_stat_m[Bc * Hc * Sc * 16];   // per-tile row max   (4MB)
__device__ float g_stat_s[Bc * Hc * Sc * 16];   // per-tile row sumexp(4MB)
__device__ float g_row_m[Bc * Hc * Sc];         // per-row global max
__device__ float g_row_inv[Bc * Hc * Sc];       // per-row 1/sum
__device__ int   g_mask_mode;   // 0 = uint8, 1 = int32, 2 = float32

// ---------------------------------------------------------------------------
// TF32 helpers — 3xTF32 error compensation (x = hi + lo, hi=tf32(x),
// lo=tf32(x-hi); product = hi*hi + hi*lo + lo*hi, error ~2^-22)
// ---------------------------------------------------------------------------
__device__ __forceinline__ unsigned cvt1(float v) {
    unsigned o;
    asm("cvt.rna.tf32.f32 %0, %1;" : "=r"(o) : "f"(v));
    return o;
}

__device__ __forceinline__ void split4(float4 v, uint4& hi, uint4& lo) {
    hi.x = cvt1(v.x); lo.x = cvt1(v.x - __uint_as_float(hi.x));
    hi.y = cvt1(v.y); lo.y = cvt1(v.y - __uint_as_float(hi.y));
    hi.z = cvt1(v.z); lo.z = cvt1(v.z - __uint_as_float(hi.z));
    hi.w = cvt1(v.w); lo.w = cvt1(v.w - __uint_as_float(hi.w));
}

// D(16x8) += A(16x8) * B(8x8), A row-major frag, B col-major frag
__device__ __forceinline__ void mma_tf32(float (&d)[4], const unsigned (&a)[4],
                                         const unsigned (&b)[2]) {
    asm volatile(
        "mma.sync.aligned.m16n8k8.row.col.f32.tf32.tf32.f32 "
        "{%0,%1,%2,%3}, {%4,%5,%6,%7}, {%8,%9}, {%0,%1,%2,%3};\n"
        : "+f"(d[0]), "+f"(d[1]), "+f"(d[2]), "+f"(d[3])
        : "r"(a[0]), "r"(a[1]), "r"(a[2]), "r"(a[3]), "r"(b[0]), "r"(b[1]));
}

// 3-term compensated MMA
__device__ __forceinline__ void mma3(float (&d)[4],
                                     const unsigned (&ah)[4], const unsigned (&al)[4],
                                     const unsigned (&bh)[2], const unsigned (&bl)[2]) {
    mma_tf32(d, ah, bh);
    mma_tf32(d, ah, bl);
    mma_tf32(d, al, bh);
}

// ---------------------------------------------------------------------------
// Mask dtype detection: read first 4096 BYTES (in-bounds for all encodings).
// ---------------------------------------------------------------------------
__global__ void detect_mask_kernel(const unsigned int* __restrict__ m) {
    int t = threadIdx.x;
    int gt1 = 0, f1 = 0;
    #pragma unroll
    for (int i = 0; i < 4; i++) {
        unsigned int x = m[t * 4 + i];
        if (x > 1u && x != 0x3F800000u) gt1 = 1;
        if (x == 0x3F800000u) f1 = 1;
    }
    int any_gt1 = __syncthreads_or(gt1);
    int any_f1  = __syncthreads_or(f1);
    if (t == 0) {
        int mode;
        if (any_gt1)     mode = 0;   // packed bytes
        else if (any_f1) mode = 2;   // float 0.0 / 1.0
        else             mode = 1;   // int32 0 / 1
        g_mask_mode = mode;
    }
}

// ---------------------------------------------------------------------------
// Projection GEMM: C[4096x1024] = A[4096x1024] @ W[1024x1024] + bias
// BM=128, BN=128, BK=16, 256 threads = 8 warps (2m x 4n), warp tile 64x32.
// 3xTF32 compensated.
// ---------------------------------------------------------------------------
__global__ void __launch_bounds__(256)
proj_gemm_kernel(const float* __restrict__ A, const float* __restrict__ W,
                 const float* __restrict__ bias, float* __restrict__ C)
{
    const int K = Dc, lda = Dc, ldb = Dc, ldc = Dc;
    const int row0 = blockIdx.y * 128, col0 = blockIdx.x * 128;

    __shared__ unsigned AsH[128][20], AsL[128][20];   // [m][k]
    __shared__ unsigned BsH[16][136], BsL[16][136];   // [k][n]

    const int t = threadIdx.x;
    const int lane = t & 31, warp = t >> 5;
    const int wm = warp >> 2, wn = warp & 3;
    const int r = lane >> 2, c = lane & 3;

    float acc[4][4][4];
    #pragma unroll
    for (int i = 0; i < 4; i++)
        #pragma unroll
        for (int j = 0; j < 4; j++)
            #pragma unroll
            for (int l = 0; l < 4; l++) acc[i][j][l] = 0.f;

    const int arow = t >> 2, ac4 = (t & 3) << 2;   // + i*64 rows
    const int bk   = t >> 5, bn4 = (t & 31) << 2;  // + i*8 k-rows

    float4 pa[2], pb[2];
    #pragma unroll
    for (int i = 0; i < 2; i++) {
        pa[i] = *(const float4*)(A + (size_t)(row0 + arow + i * 64) * lda + ac4);
        pb[i] = *(const float4*)(W + (size_t)(bk + i * 8) * ldb + col0 + bn4);
    }

    for (int k0 = 0; k0 < K; k0 += 16) {
        #pragma unroll
        for (int i = 0; i < 2; i++) {
            uint4 hi, lo;
            split4(pa[i], hi, lo);
            *(uint4*)&AsH[arow + i * 64][ac4] = hi;
            *(uint4*)&AsL[arow + i * 64][ac4] = lo;
            split4(pb[i], hi, lo);
            *(uint4*)&BsH[bk + i * 8][bn4] = hi;
            *(uint4*)&BsL[bk + i * 8][bn4] = lo;
        }
        __syncthreads();
        if (k0 + 16 < K) {
            #pragma unroll
            for (int i = 0; i < 2; i++) {
                pa[i] = *(const float4*)(A + (size_t)(row0 + arow + i * 64) * lda + k0 + 16 + ac4);
                pb[i] = *(const float4*)(W + (size_t)(k0 + 16 + bk + i * 8) * ldb + col0 + bn4);
            }
        }
        #pragma unroll
        for (int ks = 0; ks < 2; ks++) {
            unsigned afh[4][4], afl[4][4], bfh[4][2], bfl[4][2];
            #pragma unroll
            for (int mi = 0; mi < 4; mi++) {
                int m = wm * 64 + mi * 16;
                afh[mi][0] = AsH[m + r][ks * 8 + c];
                afh[mi][1] = AsH[m + r + 8][ks * 8 + c];
                afh[mi][2] = AsH[m + r][ks * 8 + c + 4];
                afh[mi][3] = AsH[m + r + 8][ks * 8 + c + 4];
                afl[mi][0] = AsL[m + r][ks * 8 + c];
                afl[mi][1] = AsL[m + r + 8][ks * 8 + c];
                afl[mi][2] = AsL[m + r][ks * 8 + c + 4];
                afl[mi][3] = AsL[m + r + 8][ks * 8 + c + 4];
            }
            #pragma unroll
            for (int ni = 0; ni < 4; ni++) {
                int n = wn * 32 + ni * 8 + r;
                bfh[ni][0] = BsH[ks * 8 + c][n];
                bfh[ni][1] = BsH[ks * 8 + c + 4][n];
                bfl[ni][0] = BsL[ks * 8 + c][n];
                bfl[ni][1] = BsL[ks * 8 + c + 4][n];
            }
            #pragma unroll
            for (int mi = 0; mi < 4; mi++)
                #pragma unroll
                for (int ni = 0; ni < 4; ni++)
                    mma3(acc[mi][ni], afh[mi], afl[mi], bfh[ni], bfl[ni]);
        }
        __syncthreads();
    }

    #pragma unroll
    for (int mi = 0; mi < 4; mi++) {
        #pragma unroll
        for (int ni = 0; ni < 4; ni++) {
            int col = col0 + wn * 32 + ni * 8 + c * 2;
            float2 bv = *(const float2*)(bias + col);
            int row = row0 + wm * 64 + mi * 16 + r;
            float2 o0 = { acc[mi][ni][0] + bv.x, acc[mi][ni][1] + bv.y };
            float2 o1 = { acc[mi][ni][2] + bv.x, acc[mi][ni][3] + bv.y };
            *(float2*)(C + (size_t)row * ldc + col) = o0;
            *(float2*)(C + (size_t)(row + 8) * ldc + col) = o1;
        }
    }
}

// ---------------------------------------------------------------------------
// Scores: attn_raw[z,qi,kj] = mask[b,kj] ? (q.k)/8 : -inf  (raw, pre-softmax)
// Also emits per-(row, 128-col-tile) online-softmax stats (max, sumexp).
// BM=128 (q), BN=128 (k), head-dim 64 as FOUR 16-wide chunks (hi+lo smem).
// grid (16, 16, 32). 3xTF32 compensated.
// ---------------------------------------------------------------------------
__global__ void __launch_bounds__(256)
scores_tc_kernel(const float* __restrict__ q, const float* __restrict__ k,
                 const void* __restrict__ maskp, float* __restrict__ attn)
{
    __shared__ unsigned QsH[128][20], QsL[128][20];   // [m][k-chunk 16]
    __shared__ unsigned KtH[16][136], KtL[16][136];   // [k-chunk][n]
    __shared__ float sm_m[128][4];     // per-row per-warpcol max
    __shared__ float sm_s[128][4];     // per-row per-warpcol sumexp

    const int z = blockIdx.z, b = z >> 4, h = z & 15;
    const int m0 = blockIdx.y * 128, n0 = blockIdx.x * 128;
    const int t = threadIdx.x, lane = t & 31, warp = t >> 5;
    const int wm = warp >> 2, wn = warp & 3;
    const int r = lane >> 2, c = lane & 3;

    const float* qb = q + ((size_t)b * Sc + m0) * Dc + h * DHc;
    const float* kb = k + ((size_t)b * Sc + n0) * Dc + h * DHc;

    float acc[4][4][4];
    #pragma unroll
    for (int i = 0; i < 4; i++)
        #pragma unroll
        for (int j = 0; j < 4; j++)
            #pragma unroll
            for (int l = 0; l < 4; l++) acc[i][j][l] = 0.f;

    for (int kc = 0; kc < 4; kc++) {
        // Q chunk: 128 rows x 16 k  (512 float4, 2 iters)
        #pragma unroll
        for (int i = 0; i < 2; i++) {
            int idx = t + i * 256;
            int row = idx >> 2, c4 = (idx & 3) << 2;
            float4 v = *(const float4*)(qb + (size_t)row * Dc + kc * 16 + c4);
            uint4 hi, lo;
            split4(v, hi, lo);
            *(uint4*)&QsH[row][c4] = hi;
            *(uint4*)&QsL[row][c4] = lo;
        }
        // K chunk transposed: 16 k x 128 n (512 float4, 2 iters)
        #pragma unroll
        for (int i = 0; i < 2; i++) {
            int idx = t + i * 256;
            int n = idx & 127, kk4 = (idx >> 7) << 2;
            float4 v = *(const float4*)(kb + (size_t)n * Dc + kc * 16 + kk4);
            uint4 hi, lo;
            split4(v, hi, lo);
            KtH[kk4 + 0][n] = hi.x; KtH[kk4 + 1][n] = hi.y;
            KtH[kk4 + 2][n] = hi.z; KtH[kk4 + 3][n] = hi.w;
            KtL[kk4 + 0][n] = lo.x; KtL[kk4 + 1][n] = lo.y;
            KtL[kk4 + 2][n] = lo.z; KtL[kk4 + 3][n] = lo.w;
        }
        __syncthreads();

        #pragma unroll
        for (int ks = 0; ks < 2; ks++) {
            unsigned afh[4][4], afl[4][4], bfh[4][2], bfl[4][2];
            #pragma unroll
            for (int mi = 0; mi < 4; mi++) {
                int m = wm * 64 + mi * 16;
                afh[mi][0] = QsH[m + r][ks * 8 + c];
                afh[mi][1] = QsH[m + r + 8][ks * 8 + c];
                afh[mi][2] = QsH[m + r][ks * 8 + c + 4];
                afh[mi][3] = QsH[m + r + 8][ks * 8 + c + 4];
                afl[mi][0] = QsL[m + r][ks * 8 + c];
                afl[mi][1] = QsL[m + r + 8][ks * 8 + c];
                afl[mi][2] = QsL[m + r][ks * 8 + c + 4];
                afl[mi][3] = QsL[m + r + 8][ks * 8 + c + 4];
            }
            #pragma unroll
            for (int ni = 0; ni < 4; ni++) {
                int n = wn * 32 + ni * 8 + r;
                bfh[ni][0] = KtH[ks * 8 + c][n];
                bfh[ni][1] = KtH[ks * 8 + c + 4][n];
                bfl[ni][0] = KtL[ks * 8 + c][n];
                bfl[ni][1] = KtL[ks * 8 + c + 4][n];
            }
            #pragma unroll
            for (int mi = 0; mi < 4; mi++)
                #pragma unroll
                for (int ni = 0; ni < 4; ni++)
                    mma3(acc[mi][ni], afh[mi], afl[mi], bfh[ni], bfl[ni]);
        }
        __syncthreads();
    }

    // ---- epilogue: mask + scale in place ----
    const int mode = g_mask_mode;
    bool mv[4][2];
    #pragma unroll
    for (int ni = 0; ni < 4; ni++) {
        #pragma unroll
        for (int j = 0; j < 2; j++) {
            int kj = n0 + wn * 32 + ni * 8 + c * 2 + j;
            size_t mi_ = (size_t)b * Sc + kj;
            if (mode == 0)      mv[ni][j] = ((const unsigned char*)maskp)[mi_] != 0;
            else if (mode == 1) mv[ni][j] = ((const int*)maskp)[mi_] != 0;
            else                mv[ni][j] = ((const float*)maskp)[mi_] != 0.0f;
        }
    }
    const float scale = 0.125f;   // 1/sqrt(64)
    #pragma unroll
    for (int mi = 0; mi < 4; mi++)
        #pragma unroll
        for (int ni = 0; ni < 4; ni++) {
            acc[mi][ni][0] = mv[ni][0] ? acc[mi][ni][0] * scale : -INFINITY;
            acc[mi][ni][1] = mv[ni][1] ? acc[mi][ni][1] * scale : -INFINITY;
            acc[mi][ni][2] = mv[ni][0] ? acc[mi][ni][2] * scale : -INFINITY;
            acc[mi][ni][3] = mv[ni][1] ? acc[mi][ni][3] * scale : -INFINITY;
        }

    // ---- store raw scores ----
    float* ab = attn + (size_t)z * Sc * Sc;
    #pragma unroll
    for (int mi = 0; mi < 4; mi++) {
        #pragma unroll
        for (int ni = 0; ni < 4; ni++) {
            int qi = m0 + wm * 64 + mi * 16 + r;
            int kj = n0 + wn * 32 + ni * 8 + c * 2;
            float2 o0 = { acc[mi][ni][0], acc[mi][ni][1] };
            float2 o1 = { acc[mi][ni][2], acc[mi][ni][3] };
            *(float2*)(ab + (size_t)qi * Sc + kj) = o0;
            *(float2*)(ab + (size_t)(qi + 8) * Sc + kj) = o1;
        }
    }

    // ---- per-tile row stats: phase A = max ----
    #pragma unroll
    for (int mi = 0; mi < 4; mi++) {
        #pragma unroll
        for (int hh = 0; hh < 2; hh++) {
            float lm = -INFINITY;
            #pragma unroll
            for (int ni = 0; ni < 4; ni++)
                lm = fmaxf(lm, fmaxf(acc[mi][ni][2 * hh], acc[mi][ni][2 * hh + 1]));
            lm = fmaxf(lm, __shfl_xor_sync(0xffffffffu, lm, 1));
            lm = fmaxf(lm, __shfl_xor_sync(0xffffffffu, lm, 2));
            if (c == 0) sm_m[wm * 64 + mi * 16 + r + hh * 8][wn] = lm;
        }
    }
    __syncthreads();

    // ---- phase B = sumexp vs block row max ----
    #pragma unroll
    for (int mi = 0; mi < 4; mi++) {
        #pragma unroll
        for (int hh = 0; hh < 2; hh++) {
            int rl = wm * 64 + mi * 16 + r + hh * 8;
            float rm = fmaxf(fmaxf(sm_m[rl][0], sm_m[rl][1]),
                             fmaxf(sm_m[rl][2], sm_m[rl][3]));
            float ls = 0.f;
            if (rm != -INFINITY) {
                #pragma unroll
                for (int ni = 0; ni < 4; ni++) {
                    ls += __expf(acc[mi][ni][2 * hh]     - rm);
                    ls += __expf(acc[mi][ni][2 * hh + 1] - rm);
                }
            }
            ls += __shfl_xor_sync(0xffffffffu, ls, 1);
            ls += __shfl_xor_sync(0xffffffffu, ls, 2);
            if (c == 0) sm_s[rl][wn] = ls;
        }
    }
    __syncthreads();

    // ---- writer: one thread per row ----
    if (t < 128) {
        float rm = fmaxf(fmaxf(sm_m[t][0], sm_m[t][1]),
                         fmaxf(sm_m[t][2], sm_m[t][3]));
        float rs = sm_s[t][0] + sm_s[t][1] + sm_s[t][2] + sm_s[t][3];
        size_t row = (size_t)z * Sc + m0 + t;
        g_stat_m[row * 16 + blockIdx.x] = rm;
        g_stat_s[row * 16 + blockIdx.x] = rs;
    }
}

// ---------------------------------------------------------------------------
// Combine per-tile stats -> global row max + 1/sum. One thread per row.
// ---------------------------------------------------------------------------
__global__ void __launch_bounds__(256)
combine_stats_kernel()
{
    int row = blockIdx.x * 256 + threadIdx.x;   // 0 .. 65535
    const float* pm = g_stat_m + (size_t)row * 16;
    const float* ps = g_stat_s + (size_t)row * 16;
    float M = -INFINITY;
    #pragma unroll
    for (int i = 0; i < 16; i++) M = fmaxf(M, pm[i]);
    float S = 0.f;
    #pragma unroll
    for (int i = 0; i < 16; i++) {
        float m = pm[i];
        if (m != -INFINITY) S += __expf(m - M) * ps[i];
    }
    g_row_m[row]   = M;
    g_row_inv[row] = 1.0f / S;
}

// ---------------------------------------------------------------------------
// ctx = softmax(raw) @ V per (b,h), fused: reads raw scores, applies
// exp(v-M)*invS on the fly, writes normalized attn AND computes ctx.
// BM=64, BN=64, BK=16, 128 threads = 4 warps (2m x 2n). 3xTF32. grid (1,32,32).
// ---------------------------------------------------------------------------
__global__ void __launch_bounds__(128)
ctx_tc_kernel(float* __restrict__ attn, const float* __restrict__ v,
              float* __restrict__ ctx)
{
    const int z = blockIdx.z, b = z >> 4, h = z & 15;
    const int m0 = blockIdx.y * 64;

    __shared__ unsigned AsH[64][20], AsL[64][20];   // [m][k]
    __shared__ unsigned BsH[16][72], BsL[16][72];   // [k][n]

    const int t = threadIdx.x, lane = t & 31, warp = t >> 5;
    const int wm = warp >> 1, wn = warp & 1;
    const int r = lane >> 2, c = lane & 3;

    float* Ab = attn + (size_t)z * Sc * Sc + (size_t)m0 * Sc;
    const float* Vb = v + (size_t)b * Sc * Dc + h * DHc;

    const int arow = t >> 2, ac4 = (t & 3) << 2;   // + i*32 rows
    const int bk   = t >> 4, bn4 = (t & 15) << 2;  // + i*8 k-rows

    // softmax row constants for this thread's two A-load rows
    float Mr[2], Ir[2];
    #pragma unroll
    for (int i = 0; i < 2; i++) {
        size_t row = (size_t)z * Sc + m0 + arow + i * 32;
        Mr[i] = g_row_m[row];
        Ir[i] = g_row_inv[row];
    }

    float acc[2][4][4];
    #pragma unroll
    for (int i = 0; i < 2; i++)
        #pragma unroll
        for (int j = 0; j < 4; j++)
            #pragma unroll
            for (int l = 0; l < 4; l++) acc[i][j][l] = 0.f;

    float4 pa[2], pb[2];
    #pragma unroll
    for (int i = 0; i < 2; i++) {
        pa[i] = *(const float4*)(Ab + (size_t)(arow + i * 32) * Sc + ac4);
        pb[i] = *(const float4*)(Vb + (size_t)(bk + i * 8) * Dc + bn4);
    }

    for (int k0 = 0; k0 < Sc; k0 += 16) {
        #pragma unroll
        for (int i = 0; i < 2; i++) {
            float4 raw = pa[i];
            float4 p;
            p.x = __expf(raw.x - Mr[i]) * Ir[i];
            p.y = __expf(raw.y - Mr[i]) * Ir[i];
            p.z = __expf(raw.z - Mr[i]) * Ir[i];
            p.w = __expf(raw.w - Mr[i]) * Ir[i];
            *(float4*)(Ab + (size_t)(arow + i * 32) * Sc + k0 + ac4) = p;
            uint4 hi, lo;
            split4(p, hi, lo);
            *(uint4*)&AsH[arow + i * 32][ac4] = hi;
            *(uint4*)&AsL[arow + i * 32][ac4] = lo;
            split4(pb[i], hi, lo);
            *(uint4*)&BsH[bk + i * 8][bn4] = hi;
            *(uint4*)&BsL[bk + i * 8][bn4] = lo;
        }
        __syncthreads();
        if (k0 + 16 < Sc) {
            #pragma unroll
            for (int i = 0; i < 2; i++) {
                pa[i] = *(const float4*)(Ab + (size_t)(arow + i * 32) * Sc + k0 + 16 + ac4);
                pb[i] = *(const float4*)(Vb + (size_t)(k0 + 16 + bk + i * 8) * Dc + bn4);
            }
        }
        #pragma unroll
        for (int ks = 0; ks < 2; ks++) {
            unsigned afh[2][4], afl[2][4], bfh[4][2], bfl[4][2];
            #pragma unroll
            for (int mi = 0; mi < 2; mi++) {
                int m = wm * 32 + mi * 16;
                afh[mi][0] = AsH[m + r][ks * 8 + c];
                afh[mi][1] = AsH[m + r + 8][ks * 8 + c];
                afh[mi][2] = AsH[m + r][ks * 8 + c + 4];
                afh[mi][3] = AsH[m + r + 8][ks * 8 + c + 4];
                afl[mi][0] = AsL[m + r][ks * 8 + c];
                afl[mi][1] = AsL[m + r + 8][ks * 8 + c];
                afl[mi][2] = AsL[m + r][ks * 8 + c + 4];
                afl[mi][3] = AsL[m + r + 8][ks * 8 + c + 4];
            }
            #pragma unroll
            for (int ni = 0; ni < 4; ni++) {
                int n = wn * 32 + ni * 8 + r;
                bfh[ni][0] = BsH[ks * 8 + c][n];
                bfh[ni][1] = BsH[ks * 8 + c + 4][n];
                bfl[ni][0] = BsL[ks * 8 + c][n];
                bfl[ni][1] = BsL[ks * 8 + c + 4][n];
            }
            #pragma unroll
            for (int mi = 0; mi < 2; mi++)
                #pragma unroll
                for (int ni = 0; ni < 4; ni++)
                    mma3(acc[mi][ni], afh[mi], afl[mi], bfh[ni], bfl[ni]);
        }
        __syncthreads();
    }

    #pragma unroll
    for (int mi = 0; mi < 2; mi++) {
        #pragma unroll
        for (int ni = 0; ni < 4; ni++) {
            int row = m0 + wm * 32 + mi * 16 + r;
            int col = h * DHc + wn * 32 + ni * 8 + c * 2;
            float2 o0 = { acc[mi][ni][0], acc[mi][ni][1] };
            float2 o1 = { acc[mi][ni][2], acc[mi][ni][3] };
            *(float2*)(ctx + ((size_t)b * Sc + row) * Dc + col) = o0;
            *(float2*)(ctx + ((size_t)b * Sc + row + 8) * Dc + col) = o1;
        }
    }
}

// ---------------------------------------------------------------------------
// Host launcher
// ---------------------------------------------------------------------------
extern "C" void kernel_launch(void* const* d_in, const int* in_sizes, int n_in,
                              void* d_out, int out_size)
{
    const float* qs  = (const float*)d_in[0];
    const float* ks  = (const float*)d_in[1];
    const float* vs  = (const float*)d_in[2];
    const void*  msk = d_in[3];
    const float* Wq  = (const float*)d_in[4];
    const float* bq  = (const float*)d_in[5];
    const float* Wk  = (const float*)d_in[6];
    const float* bk  = (const float*)d_in[7];
    const float* Wv  = (const float*)d_in[8];
    const float* bv  = (const float*)d_in[9];
    const float* Wo  = (const float*)d_in[10];
    const float* bo  = (const float*)d_in[11];

    float* out  = (float*)d_out;
    float* attn = out + (size_t)Bc * Sc * Dc;   // tuple (out, attn) flattened

    float *gq, *gk, *gv, *gc;
    cudaGetSymbolAddress((void**)&gq, g_q);
    cudaGetSymbolAddress((void**)&gk, g_k);
    cudaGetSymbolAddress((void**)&gv, g_v);
    cudaGetSymbolAddress((void**)&gc, g_ctx);

    detect_mask_kernel<<<1, 256>>>((const unsigned int*)msk);

    dim3 gproj(Dc / 128, (Bc * Sc) / 128);        // (8, 32)
    proj_gemm_kernel<<<gproj, 256>>>(qs, Wq, bq, gq);
    proj_gemm_kernel<<<gproj, 256>>>(ks, Wk, bk, gk);
    proj_gemm_kernel<<<gproj, 256>>>(vs, Wv, bv, gv);

    dim3 gsc(Sc / 128, Sc / 128, Bc * Hc);        // (16, 16, 32)
    scores_tc_kernel<<<gsc, 256>>>(gq, gk, msk, attn);

    combine_stats_kernel<<<(Bc * Hc * Sc) / 256, 256>>>();

    dim3 gctx(1, Sc / 64, Bc * Hc);               // (1, 32, 32)
    ctx_tc_kernel<<<gctx, 128>>>(attn, gv, gc);

    proj_gemm_kernel<<<gproj, 256>>>(gc, Wo, bo, out);
}